// round 1
// baseline (speedup 1.0000x reference)
#include <cuda_runtime.h>
#include <math.h>

#define DIM 512
#define BM 128
#define BN 128
#define BK 16
#define TM 8
#define TN 8
#define P_MAX 2048
#define R_MAX 65536

// Scratch (no allocations allowed): norms + global min (encoded as ordered uint).
__device__ float g_xn[P_MAX];
__device__ float g_yn[R_MAX];
__device__ unsigned int g_min_bits;

// Monotone float <-> uint encoding so atomicMin(uint) orders floats correctly
// (handles the slightly-negative sq values from cancellation).
__device__ __forceinline__ unsigned int enc_f(float f) {
    unsigned int u = __float_as_uint(f);
    return (u & 0x80000000u) ? ~u : (u | 0x80000000u);
}
__device__ __forceinline__ float dec_f(unsigned int u) {
    return (u & 0x80000000u) ? __uint_as_float(u & 0x7FFFFFFFu)
                             : __uint_as_float(~u);
}

// Kernel 0: reset the global min and compute row norms for x and y.
__global__ void norms_kernel(const float* __restrict__ x,
                             const float* __restrict__ y,
                             int P, int R) {
    int row = blockIdx.x * blockDim.x + threadIdx.x;
    if (row == 0) g_min_bits = 0xFFFFFFFFu;  // enc(+inf-ish): max uint
    int total = P + R;
    if (row >= total) return;
    const float* src = (row < P) ? (x + (size_t)row * DIM)
                                 : (y + (size_t)(row - P) * DIM);
    const float4* s4 = reinterpret_cast<const float4*>(src);
    float acc = 0.f;
#pragma unroll 8
    for (int i = 0; i < DIM / 4; i++) {
        float4 v = s4[i];
        acc += v.x * v.x + v.y * v.y + v.z * v.z + v.w * v.w;
    }
    if (row < P) g_xn[row] = acc;
    else         g_yn[row - P] = acc;
}

// Kernel 1: tiled "GEMM" computing dot(x_p, y_r); epilogue forms
// sq = |x|^2 + |y|^2 - 2*dot and block-reduces the min into g_min_bits.
__global__ void __launch_bounds__(256, 2)
min_dist_kernel(const float* __restrict__ x,
                const float* __restrict__ y,
                int P, int R) {
    __shared__ float As[BK][BM];  // transposed x tile: As[k][m]
    __shared__ float Bs[BK][BN];  // transposed y tile: Bs[k][n]

    const int bm = blockIdx.y * BM;   // offset into P
    const int bn = blockIdx.x * BN;   // offset into R
    const int tid = threadIdx.x;
    const int tx = tid % (BN / TN);   // 0..15  (N direction)
    const int ty = tid / (BN / TN);   // 0..15  (M direction)

    float acc[TM][TN];
#pragma unroll
    for (int i = 0; i < TM; i++)
#pragma unroll
        for (int j = 0; j < TN; j++) acc[i][j] = 0.f;

    for (int k0 = 0; k0 < DIM; k0 += BK) {
        // Load x tile: BM x BK = 2048 floats = 512 float4; 2 per thread.
#pragma unroll
        for (int l = 0; l < 2; l++) {
            int j = tid + l * 256;           // 0..511
            int row = j >> 2;                // 0..127
            int c4  = (j & 3) * 4;           // 0,4,8,12
            float4 v = *reinterpret_cast<const float4*>(
                x + (size_t)(bm + row) * DIM + k0 + c4);
            As[c4 + 0][row] = v.x;
            As[c4 + 1][row] = v.y;
            As[c4 + 2][row] = v.z;
            As[c4 + 3][row] = v.w;
        }
        // Load y tile: BN x BK, same layout.
#pragma unroll
        for (int l = 0; l < 2; l++) {
            int j = tid + l * 256;
            int row = j >> 2;
            int c4  = (j & 3) * 4;
            float4 v = *reinterpret_cast<const float4*>(
                y + (size_t)(bn + row) * DIM + k0 + c4);
            Bs[c4 + 0][row] = v.x;
            Bs[c4 + 1][row] = v.y;
            Bs[c4 + 2][row] = v.z;
            Bs[c4 + 3][row] = v.w;
        }
        __syncthreads();

#pragma unroll
        for (int k = 0; k < BK; k++) {
            float ra[TM], rb[TN];
            *reinterpret_cast<float4*>(&ra[0]) =
                *reinterpret_cast<const float4*>(&As[k][ty * TM]);
            *reinterpret_cast<float4*>(&ra[4]) =
                *reinterpret_cast<const float4*>(&As[k][ty * TM + 4]);
            *reinterpret_cast<float4*>(&rb[0]) =
                *reinterpret_cast<const float4*>(&Bs[k][tx * TN]);
            *reinterpret_cast<float4*>(&rb[4]) =
                *reinterpret_cast<const float4*>(&Bs[k][tx * TN + 4]);
#pragma unroll
            for (int i = 0; i < TM; i++)
#pragma unroll
                for (int j = 0; j < TN; j++)
                    acc[i][j] = fmaf(ra[i], rb[j], acc[i][j]);
        }
        __syncthreads();
    }

    // Epilogue: sq = xn + yn - 2*dot; thread-local min.
    float xnr[TM], ynr[TN];
#pragma unroll
    for (int i = 0; i < TM; i++) xnr[i] = g_xn[bm + ty * TM + i];
#pragma unroll
    for (int j = 0; j < TN; j++) ynr[j] = g_yn[bn + tx * TN + j];

    float m = 3.4e38f;
#pragma unroll
    for (int i = 0; i < TM; i++)
#pragma unroll
        for (int j = 0; j < TN; j++) {
            float sq = fmaf(-2.0f, acc[i][j], xnr[i] + ynr[j]);
            m = fminf(m, sq);
        }

    // Warp reduce, then one atomic per warp (8 per block; contention negligible).
#pragma unroll
    for (int off = 16; off > 0; off >>= 1)
        m = fminf(m, __shfl_xor_sync(0xFFFFFFFFu, m, off));
    if ((tid & 31) == 0)
        atomicMin(&g_min_bits, enc_f(m));
}

// Kernel 2: finalize -> sqrt(max(min_sq, 0))
__global__ void finalize_kernel(float* __restrict__ out) {
    float sq = dec_f(g_min_bits);
    out[0] = sqrtf(fmaxf(sq, 0.0f));
}

extern "C" void kernel_launch(void* const* d_in, const int* in_sizes, int n_in,
                              void* d_out, int out_size) {
    const float* x = (const float*)d_in[0];  // [1, P, 512]
    const float* y = (const float*)d_in[1];  // [1, R, 512]
    int P = in_sizes[0] / DIM;
    int R = in_sizes[1] / DIM;

    int total = P + R;
    norms_kernel<<<(total + 255) / 256, 256>>>(x, y, P, R);

    dim3 grid(R / BN, P / BM);  // (512, 16) for the fixed shapes
    min_dist_kernel<<<grid, 256>>>(x, y, P, R);

    finalize_kernel<<<1, 1>>>((float*)d_out);
}